// round 8
// baseline (speedup 1.0000x reference)
#include <cuda_runtime.h>
#include <cuda_bf16.h>
#include <cstdint>

// ---------------------------------------------------------------------------
// Problem constants
// ---------------------------------------------------------------------------
#define BATCHN  8
#define SEQL    1024
#define EMB     768
#define NH      12
#define HD      64
#define ROWS    (BATCHN*SEQL)        // 8192
#define QKVC    (3*EMB)              // 2304
#define ZTOT    (BATCHN*NH)          // 96
#define AROWS   (ZTOT*SEQL)          // 98304
#define K_SCALE 0.125f
#define EXP_OFF 20.0f

// ---------------------------------------------------------------------------
// Device scratch (static globals; allocation-free)
// ---------------------------------------------------------------------------
__device__ __align__(16) __nv_bfloat16 g_x_hi  [ROWS*EMB];
__device__ __align__(16) __nv_bfloat16 g_x_lo  [ROWS*EMB];
__device__ __align__(16) __nv_bfloat16 g_wqkv_hi[QKVC*EMB];
__device__ __align__(16) __nv_bfloat16 g_wqkv_lo[QKVC*EMB];
__device__ __align__(16) __nv_bfloat16 g_wp_hi [EMB*EMB];
__device__ __align__(16) __nv_bfloat16 g_wp_lo [EMB*EMB];
__device__ __align__(16) __nv_bfloat16 g_qkv_hi[(size_t)ROWS*QKVC];
__device__ __align__(16) __nv_bfloat16 g_qkv_lo[(size_t)ROWS*QKVC];
__device__ __align__(16) __nv_bfloat16 g_p_hi  [(size_t)ZTOT*SEQL*SEQL];
__device__ __align__(16) __nv_bfloat16 g_p_lo  [(size_t)ZTOT*SEQL*SEQL];
__device__ __align__(16) __nv_bfloat16 g_oh_hi [ROWS*EMB];
__device__ __align__(16) __nv_bfloat16 g_oh_lo [ROWS*EMB];
__device__ float g_psum[(size_t)AROWS*64];
__device__ float g_inv [AROWS];

// ---------------------------------------------------------------------------
// PTX helpers (all sm_80-era: safe on plain compute_103)
// ---------------------------------------------------------------------------
__device__ __forceinline__ uint32_t smem_u32(const void* p) {
    uint32_t a;
    asm("{ .reg .u64 t; cvta.to.shared.u64 t, %1; cvt.u32.u64 %0, t; }"
        : "=r"(a) : "l"(p));
    return a;
}
__device__ __forceinline__ void cp16(uint32_t dst, const void* src) {
    asm volatile("cp.async.cg.shared.global [%0], [%1], 16;"
                 :: "r"(dst), "l"(src));
}
#define CP_COMMIT() asm volatile("cp.async.commit_group;" ::: "memory")
#define CP_WAIT(n)  asm volatile("cp.async.wait_group %0;" :: "n"(n) : "memory")

__device__ __forceinline__ void ldsm_x4(uint32_t* r, uint32_t addr) {
    asm volatile("ldmatrix.sync.aligned.m8n8.x4.shared.b16 {%0,%1,%2,%3}, [%4];"
        : "=r"(r[0]), "=r"(r[1]), "=r"(r[2]), "=r"(r[3]) : "r"(addr));
}
__device__ __forceinline__ void ldsm_x2(uint32_t* r, uint32_t addr) {
    asm volatile("ldmatrix.sync.aligned.m8n8.x2.shared.b16 {%0,%1}, [%2];"
        : "=r"(r[0]), "=r"(r[1]) : "r"(addr));
}
__device__ __forceinline__ void ldsm_x2t(uint32_t* r, uint32_t addr) {
    asm volatile("ldmatrix.sync.aligned.m8n8.x2.trans.shared.b16 {%0,%1}, [%2];"
        : "=r"(r[0]), "=r"(r[1]) : "r"(addr));
}
__device__ __forceinline__ void mma_bf16(float* c, const uint32_t* a, const uint32_t* b) {
    asm volatile("mma.sync.aligned.m16n8k16.row.col.f32.bf16.bf16.f32 "
        "{%0,%1,%2,%3}, {%4,%5,%6,%7}, {%8,%9}, {%0,%1,%2,%3};"
        : "+f"(c[0]), "+f"(c[1]), "+f"(c[2]), "+f"(c[3])
        : "r"(a[0]), "r"(a[1]), "r"(a[2]), "r"(a[3]), "r"(b[0]), "r"(b[1]));
}

__device__ __forceinline__ uint32_t pack_hi(float a, float b) {
    return ((uint32_t)__bfloat16_as_ushort(__float2bfloat16(b)) << 16) |
            (uint32_t)__bfloat16_as_ushort(__float2bfloat16(a));
}
__device__ __forceinline__ uint32_t pack_lo(float a, float b) {
    __nv_bfloat16 ha = __float2bfloat16(a), hb = __float2bfloat16(b);
    float la = a - __bfloat162float(ha), lb = b - __bfloat162float(hb);
    return ((uint32_t)__bfloat16_as_ushort(__float2bfloat16(lb)) << 16) |
            (uint32_t)__bfloat16_as_ushort(__float2bfloat16(la));
}

// ---------------------------------------------------------------------------
// BIG-TILE projection GEMM (modes 0 and 3): 256x128 tile, warp m64 x n64,
// bf16 hi/lo 3-term split, 3-stage cp.async ring, ONE sync per K-stage.
// ---------------------------------------------------------------------------
template<int MODE>
__global__ __launch_bounds__(256)
void gemm_big(const __nv_bfloat16* __restrict__ Ahi_base,
              const __nv_bfloat16* __restrict__ Alo_base,
              const __nv_bfloat16* __restrict__ Bhi_base,
              const __nv_bfloat16* __restrict__ Blo_base,
              float* __restrict__ fout,
              __nv_bfloat16* __restrict__ ohi,
              __nv_bfloat16* __restrict__ olo,
              const float* __restrict__ bias) {
    constexpr int NSTAGE  = EMB / 32;           // 24
    constexpr int STAGES  = 3;
    constexpr int LDS     = 40;
    constexpr int A_BYTES = 256 * LDS * 2;      // 20480
    constexpr int B_BYTES = 128 * LDS * 2;      // 10240
    constexpr int STAGE_B = 2 * A_BYTES + 2 * B_BYTES;   // 61440

    extern __shared__ __align__(16) char dynsmem[];

    const int tid  = threadIdx.x;
    const int lane = tid & 31;
    const int wid  = tid >> 5;
    const int wm   = wid & 3;
    const int wn   = wid >> 2;
    const int l15  = lane & 15;
    const int bx = blockIdx.x, by = blockIdx.y;

    const __nv_bfloat16* Ah = Ahi_base + (long long)by * 256 * EMB;
    const __nv_bfloat16* Al = Alo_base + (long long)by * 256 * EMB;
    const __nv_bfloat16* Bh = Bhi_base + (long long)bx * 128 * EMB;
    const __nv_bfloat16* Bl = Blo_base + (long long)bx * 128 * EMB;

    const int arow = tid >> 2;
    const int acol = (tid & 3) * 8;

    const uint32_t sb = smem_u32(dynsmem);

    auto issue = [&](int s) {
        const uint32_t base = sb + (uint32_t)(s % STAGES) * STAGE_B;
        const long long k0 = (long long)s * 32;
        #pragma unroll
        for (int it = 0; it < 4; it++) {
            const int r = arow + it * 64;
            const uint32_t d = base + (uint32_t)(r * LDS + acol) * 2;
            cp16(d,           Ah + (long long)r * EMB + k0 + acol);
            cp16(d + A_BYTES, Al + (long long)r * EMB + k0 + acol);
        }
        #pragma unroll
        for (int it = 0; it < 2; it++) {
            const int r = arow + it * 64;
            const uint32_t d = base + 2 * A_BYTES + (uint32_t)(r * LDS + acol) * 2;
            cp16(d,           Bh + (long long)r * EMB + k0 + acol);
            cp16(d + B_BYTES, Bl + (long long)r * EMB + k0 + acol);
        }
    };

    float acc[4][8][4];
    #pragma unroll
    for (int i = 0; i < 4; i++)
        #pragma unroll
        for (int j = 0; j < 8; j++)
            #pragma unroll
            for (int e = 0; e < 4; e++) acc[i][j][e] = 0.f;

    issue(0); CP_COMMIT();
    issue(1); CP_COMMIT();

    for (int s = 0; s < NSTAGE; s++) {
        CP_WAIT(1);
        __syncthreads();                 // single barrier per stage
        if (s + 2 < NSTAGE) { issue(s + 2); CP_COMMIT(); }

        const uint32_t base = sb + (uint32_t)(s % STAGES) * STAGE_B;
        const uint32_t uAh = base;
        const uint32_t uAl = base + A_BYTES;
        const uint32_t uBh = base + 2 * A_BYTES;
        const uint32_t uBl = base + 2 * A_BYTES + B_BYTES;

        #pragma unroll
        for (int ks = 0; ks < 2; ks++) {
            uint32_t bh[8][2], bl[8][2];
            #pragma unroll
            for (int j = 0; j < 8; j++) {
                const int nr = wn * 64 + j * 8 + (l15 & 7);
                const int kc = ks * 16 + (l15 >> 3) * 8;
                const uint32_t off = (uint32_t)(nr * LDS + kc) * 2;
                ldsm_x2(bh[j], uBh + off);
                ldsm_x2(bl[j], uBl + off);
            }
            #pragma unroll
            for (int i = 0; i < 4; i++) {
                const int ar = wm * 64 + i * 16 + l15;
                const int ac = ks * 16 + (lane >> 4) * 8;
                const uint32_t aoff = (uint32_t)(ar * LDS + ac) * 2;
                uint32_t ah[4], al[4];
                ldsm_x4(ah, uAh + aoff);
                #pragma unroll
                for (int j = 0; j < 8; j++) mma_bf16(acc[i][j], ah, bh[j]);
                ldsm_x4(al, uAl + aoff);
                #pragma unroll
                for (int j = 0; j < 8; j++) mma_bf16(acc[i][j], ah, bl[j]);
                #pragma unroll
                for (int j = 0; j < 8; j++) mma_bf16(acc[i][j], al, bh[j]);
            }
        }
    }

    // ---- epilogue ----
    const int g = lane >> 2, t = lane & 3;
    #pragma unroll
    for (int i = 0; i < 4; i++) {
        const int m0 = by * 256 + wm * 64 + i * 16 + g;
        const int m1 = m0 + 8;
        #pragma unroll
        for (int j = 0; j < 8; j++) {
            const int n = bx * 128 + wn * 64 + j * 8 + 2 * t;
            const float c0 = acc[i][j][0], c1 = acc[i][j][1];
            const float c2 = acc[i][j][2], c3 = acc[i][j][3];
            if (MODE == 0) {
                long long o0 = (long long)m0 * QKVC + n;
                long long o1 = (long long)m1 * QKVC + n;
                *(uint32_t*)(ohi + o0) = pack_hi(c0, c1);
                *(uint32_t*)(olo + o0) = pack_lo(c0, c1);
                *(uint32_t*)(ohi + o1) = pack_hi(c2, c3);
                *(uint32_t*)(olo + o1) = pack_lo(c2, c3);
            } else {
                float2 w0 = { c0 + bias[n], c1 + bias[n + 1] };
                float2 w1 = { c2 + bias[n], c3 + bias[n + 1] };
                *(float2*)(fout + (long long)m0 * EMB + n) = w0;
                *(float2*)(fout + (long long)m1 * EMB + n) = w1;
            }
        }
    }
}

// ---------------------------------------------------------------------------
// Attention kernels (modes 1 and 2), 128x64 tile, one sync per stage.
// ---------------------------------------------------------------------------
template<int MODE>
__global__ __launch_bounds__(256, 2)
void mma_gemm(const __nv_bfloat16* __restrict__ Ahi_base,
              const __nv_bfloat16* __restrict__ Alo_base,
              const __nv_bfloat16* __restrict__ Bhi_base,
              const __nv_bfloat16* __restrict__ Blo_base,
              float* __restrict__ fout,
              __nv_bfloat16* __restrict__ ohi,
              __nv_bfloat16* __restrict__ olo,
              const float* __restrict__ aux) {
    constexpr int NJ      = 2;
    constexpr int KTOT    = (MODE == 1) ? 64 : 1024;
    constexpr int NSTAGE  = KTOT / 32;
    constexpr int STAGES  = (MODE == 1) ? 2 : 3;
    constexpr int LDS_A   = 40;
    constexpr int LDS_B   = (MODE == 2) ? 72 : 40;
    constexpr int A_BYTES = 128 * LDS_A * 2;
    constexpr int B_BYTES = (MODE == 2) ? 32 * LDS_B * 2 : 64 * LDS_B * 2;
    constexpr int STAGE_B = 2 * A_BYTES + 2 * B_BYTES;

    extern __shared__ __align__(16) char dynsmem[];

    const int tid  = threadIdx.x;
    const int lane = tid & 31;
    const int wid  = tid >> 5;
    const int wm   = wid >> 2;
    const int wn   = wid & 3;
    const int l15  = lane & 15;
    const int bx = blockIdx.x, by = blockIdx.y, bz = blockIdx.z;
    const int bb = bz / NH, hh = bz % NH;

    const __nv_bfloat16 *Ah, *Al, *Bh, *Bl;
    long long LDA = 0, LDB = 0;
    if (MODE == 1) {
        LDA = QKVC; LDB = QKVC;
        long long ao = ((long long)bb * SEQL + by * 128) * QKVC + hh * HD;
        long long bo = ((long long)bb * SEQL + bx * 64) * QKVC + EMB + hh * HD;
        Ah = Ahi_base + ao; Al = Alo_base + ao;
        Bh = Bhi_base + bo; Bl = Blo_base + bo;
    } else {
        LDA = SEQL; LDB = QKVC;
        long long ao = (long long)bz * SEQL * SEQL + (long long)by * 128 * SEQL;
        Ah = Ahi_base + ao; Al = Alo_base + ao;
        Bh = Bhi_base;      Bl = Blo_base;
    }
    float* attn_tile = nullptr;
    if (MODE == 2)
        attn_tile = fout + (long long)bz * SEQL * SEQL + (long long)by * 128 * SEQL;
    const long long auxbase = (MODE == 2) ? ((long long)bz * SEQL + by * 128) : 0;

    const int arow0 = tid >> 2;
    const int acol  = (tid & 3) * 8;
    const int arow1 = arow0 + 64;
    const int brow2 = tid >> 3;
    const int bcol2 = (tid & 7) * 8;

    const uint32_t sb = smem_u32(dynsmem);

    auto issue = [&](int s) {
        const uint32_t base = sb + (uint32_t)(s % STAGES) * STAGE_B;
        const long long k0 = (long long)s * 32;
        const uint32_t dA0 = base + (uint32_t)(arow0 * LDS_A + acol) * 2;
        const uint32_t dA1 = base + (uint32_t)(arow1 * LDS_A + acol) * 2;
        cp16(dA0,           Ah + (long long)arow0 * LDA + k0 + acol);
        cp16(dA1,           Ah + (long long)arow1 * LDA + k0 + acol);
        cp16(dA0 + A_BYTES, Al + (long long)arow0 * LDA + k0 + acol);
        cp16(dA1 + A_BYTES, Al + (long long)arow1 * LDA + k0 + acol);
        if (MODE != 2) {
            const uint32_t dB = base + 2 * A_BYTES + (uint32_t)(arow0 * LDS_B + acol) * 2;
            cp16(dB,           Bh + (long long)arow0 * LDB + k0 + acol);
            cp16(dB + B_BYTES, Bl + (long long)arow0 * LDB + k0 + acol);
        } else {
            long long vo = ((long long)bb * SEQL + s * 32 + brow2) * QKVC
                         + 2 * EMB + hh * HD + bcol2;
            const uint32_t dB = base + 2 * A_BYTES + (uint32_t)(brow2 * LDS_B + bcol2) * 2;
            cp16(dB,           Bh + vo);
            cp16(dB + B_BYTES, Bl + vo);
        }
    };

    float acc[4][NJ][4];
    #pragma unroll
    for (int i = 0; i < 4; i++)
        #pragma unroll
        for (int j = 0; j < NJ; j++)
            #pragma unroll
            for (int e = 0; e < 4; e++) acc[i][j][e] = 0.f;

    #pragma unroll
    for (int p = 0; p < STAGES - 1 && p < NSTAGE; p++) { issue(p); CP_COMMIT(); }

    for (int s = 0; s < NSTAGE; s++) {
        CP_WAIT(STAGES - 2);
        __syncthreads();                 // single barrier per stage
        if (s + STAGES - 1 < NSTAGE) { issue(s + STAGES - 1); CP_COMMIT(); }

        const int slot = s % STAGES;
        const uint32_t base = sb + (uint32_t)slot * STAGE_B;

        if (MODE == 2) {
            #pragma unroll
            for (int cch = 0; cch < 2; cch++) {
                const int r = (cch == 0) ? arow0 : arow1;
                const char* sp = dynsmem + slot * STAGE_B + (r * LDS_A + acol) * 2;
                uint4 vh = *(const uint4*)sp;
                uint4 vl = *(const uint4*)(sp + A_BYTES);
                const __nv_bfloat16* eh = (const __nv_bfloat16*)&vh;
                const __nv_bfloat16* el = (const __nv_bfloat16*)&vl;
                const float iv = aux[auxbase + r];
                long long ab = (long long)r * SEQL + s * 32 + acol;
                float4 o0, o1;
                o0.x = (__bfloat162float(eh[0]) + __bfloat162float(el[0])) * iv;
                o0.y = (__bfloat162float(eh[1]) + __bfloat162float(el[1])) * iv;
                o0.z = (__bfloat162float(eh[2]) + __bfloat162float(el[2])) * iv;
                o0.w = (__bfloat162float(eh[3]) + __bfloat162float(el[3])) * iv;
                o1.x = (__bfloat162float(eh[4]) + __bfloat162float(el[4])) * iv;
                o1.y = (__bfloat162float(eh[5]) + __bfloat162float(el[5])) * iv;
                o1.z = (__bfloat162float(eh[6]) + __bfloat162float(el[6])) * iv;
                o1.w = (__bfloat162float(eh[7]) + __bfloat162float(el[7])) * iv;
                *(float4*)(attn_tile + ab)     = o0;
                *(float4*)(attn_tile + ab + 4) = o1;
            }
        }

        const uint32_t uAh = base;
        const uint32_t uAl = base + A_BYTES;
        const uint32_t uBh = base + 2 * A_BYTES;
        const uint32_t uBl = base + 2 * A_BYTES + B_BYTES;

        #pragma unroll
        for (int ks = 0; ks < 2; ks++) {
            uint32_t bh[NJ][2], bl[NJ][2];
            #pragma unroll
            for (int j = 0; j < NJ; j++) {
                if (MODE == 2) {
                    const int kr = ks * 16 + l15;
                    const int nc = wn * 16 + j * 8;
                    const uint32_t off = (uint32_t)(kr * LDS_B + nc) * 2;
                    ldsm_x2t(bh[j], uBh + off);
                    ldsm_x2t(bl[j], uBl + off);
                } else {
                    const int nr = wn * 16 + j * 8 + (l15 & 7);
                    const int kc = ks * 16 + (l15 >> 3) * 8;
                    const uint32_t off = (uint32_t)(nr * LDS_B + kc) * 2;
                    ldsm_x2(bh[j], uBh + off);
                    ldsm_x2(bl[j], uBl + off);
                }
            }
            #pragma unroll
            for (int i = 0; i < 4; i++) {
                const int ar = wm * 64 + i * 16 + l15;
                const int ac = ks * 16 + (lane >> 4) * 8;
                const uint32_t aoff = (uint32_t)(ar * LDS_A + ac) * 2;
                uint32_t ah[4], al[4];
                ldsm_x4(ah, uAh + aoff);
                #pragma unroll
                for (int j = 0; j < NJ; j++) mma_bf16(acc[i][j], ah, bh[j]);
                ldsm_x4(al, uAl + aoff);
                #pragma unroll
                for (int j = 0; j < NJ; j++) mma_bf16(acc[i][j], ah, bl[j]);
                #pragma unroll
                for (int j = 0; j < NJ; j++) mma_bf16(acc[i][j], al, bh[j]);
            }
        }
    }

    // ---- epilogue ----
    const int g = lane >> 2, t = lane & 3;
    #pragma unroll
    for (int i = 0; i < 4; i++) {
        const int r0 = wm * 64 + i * 16 + g;
        const int r1 = r0 + 8;
        const int m0 = by * 128 + r0;
        const int m1 = by * 128 + r1;
        float s0 = 0.f, s1 = 0.f;
        float inv0 = 0.f, inv1 = 0.f;
        if (MODE == 2) { inv0 = aux[auxbase + r0]; inv1 = aux[auxbase + r1]; }

        #pragma unroll
        for (int j = 0; j < NJ; j++) {
            float c0 = acc[i][j][0], c1 = acc[i][j][1];
            float c2 = acc[i][j][2], c3 = acc[i][j][3];
            if (MODE == 1) {
                float v0 = __expf(fmaf(c0, K_SCALE, -EXP_OFF));
                float v1 = __expf(fmaf(c1, K_SCALE, -EXP_OFF));
                float v2 = __expf(fmaf(c2, K_SCALE, -EXP_OFF));
                float v3 = __expf(fmaf(c3, K_SCALE, -EXP_OFF));
                s0 += v0 + v1; s1 += v2 + v3;
                int n = bx * 64 + wn * 16 + j * 8 + 2 * t;
                long long o0 = ((long long)bz * SEQL + m0) * SEQL + n;
                long long o1 = ((long long)bz * SEQL + m1) * SEQL + n;
                *(uint32_t*)(ohi + o0) = pack_hi(v0, v1);
                *(uint32_t*)(olo + o0) = pack_lo(v0, v1);
                *(uint32_t*)(ohi + o1) = pack_hi(v2, v3);
                *(uint32_t*)(olo + o1) = pack_lo(v2, v3);
            } else {
                float v0 = c0 * inv0, v1 = c1 * inv0;
                float v2 = c2 * inv1, v3 = c3 * inv1;
                int n = hh * HD + wn * 16 + j * 8 + 2 * t;
                long long o0 = ((long long)bb * SEQL + m0) * EMB + n;
                long long o1 = ((long long)bb * SEQL + m1) * EMB + n;
                *(uint32_t*)(ohi + o0) = pack_hi(v0, v1);
                *(uint32_t*)(olo + o0) = pack_lo(v0, v1);
                *(uint32_t*)(ohi + o1) = pack_hi(v2, v3);
                *(uint32_t*)(olo + o1) = pack_lo(v2, v3);
            }
        }
        if (MODE == 1) {
            s0 += __shfl_xor_sync(0xffffffffu, s0, 1);
            s0 += __shfl_xor_sync(0xffffffffu, s0, 2);
            s1 += __shfl_xor_sync(0xffffffffu, s1, 1);
            s1 += __shfl_xor_sync(0xffffffffu, s1, 2);
            if (t == 0) {
                fout[((long long)bz * SEQL + m0) * 64 + bx * 4 + wn] = s0;
                fout[((long long)bz * SEQL + m1) * 64 + bx * 4 + wn] = s1;
            }
        }
    }
}

// ---------------------------------------------------------------------------
// fp32 -> bf16 hi/lo split
// ---------------------------------------------------------------------------
__global__ void split_hilo(const float* __restrict__ src,
                           __nv_bfloat16* __restrict__ hi,
                           __nv_bfloat16* __restrict__ lo, int n) {
    int i = blockIdx.x * 256 + threadIdx.x;
    if (i < n) {
        float v = src[i];
        __nv_bfloat16 h = __float2bfloat16(v);
        hi[i] = h;
        lo[i] = __float2bfloat16(v - __bfloat162float(h));
    }
}

// 64 partials per row -> 1/sum
__global__ void inv_rows(const float* __restrict__ psum, float* __restrict__ inv) {
    int r = blockIdx.x * 256 + threadIdx.x;
    if (r < AROWS) {
        float s = 0.f;
        #pragma unroll
        for (int j = 0; j < 64; j++) s += psum[(long long)r * 64 + j];
        inv[r] = 1.0f / s;
    }
}

// ---------------------------------------------------------------------------
// Launch
// ---------------------------------------------------------------------------
extern "C" void kernel_launch(void* const* d_in, const int* in_sizes, int n_in,
                              void* d_out, int out_size) {
    (void)in_sizes; (void)n_in; (void)out_size;
    const float* x      = (const float*)d_in[0];
    const float* w_qkv  = (const float*)d_in[1];
    const float* w_proj = (const float*)d_in[2];
    const float* b_proj = (const float*)d_in[3];

    float* out  = (float*)d_out;
    float* attn = out + (long long)ROWS * EMB;

    __nv_bfloat16 *xh, *xl, *wqh, *wql, *wph, *wpl, *qh, *ql, *ph, *pl, *ohh, *ohl;
    float *psum, *inv;
    cudaGetSymbolAddress((void**)&xh,  g_x_hi);    cudaGetSymbolAddress((void**)&xl,  g_x_lo);
    cudaGetSymbolAddress((void**)&wqh, g_wqkv_hi); cudaGetSymbolAddress((void**)&wql, g_wqkv_lo);
    cudaGetSymbolAddress((void**)&wph, g_wp_hi);   cudaGetSymbolAddress((void**)&wpl, g_wp_lo);
    cudaGetSymbolAddress((void**)&qh,  g_qkv_hi);  cudaGetSymbolAddress((void**)&ql,  g_qkv_lo);
    cudaGetSymbolAddress((void**)&ph,  g_p_hi);    cudaGetSymbolAddress((void**)&pl,  g_p_lo);
    cudaGetSymbolAddress((void**)&ohh, g_oh_hi);   cudaGetSymbolAddress((void**)&ohl, g_oh_lo);
    cudaGetSymbolAddress((void**)&psum, g_psum);   cudaGetSymbolAddress((void**)&inv,  g_inv);

    constexpr int SMBIG = 3 * 61440;  // 184320
    constexpr int SM1   = 2 * 30720;  //  61440
    constexpr int SM2   = 3 * 29696;  //  89088
    static bool attr_done = false;
    if (!attr_done) {
        cudaFuncSetAttribute(gemm_big<0>, cudaFuncAttributeMaxDynamicSharedMemorySize, SMBIG);
        cudaFuncSetAttribute(gemm_big<3>, cudaFuncAttributeMaxDynamicSharedMemorySize, SMBIG);
        cudaFuncSetAttribute(mma_gemm<1>, cudaFuncAttributeMaxDynamicSharedMemorySize, SM1);
        cudaFuncSetAttribute(mma_gemm<2>, cudaFuncAttributeMaxDynamicSharedMemorySize, SM2);
        attr_done = true;
    }

    // 0) hi/lo splits of fp32 inputs
    split_hilo<<<(ROWS*EMB + 255)/256, 256>>>(x, xh, xl, ROWS*EMB);
    split_hilo<<<(QKVC*EMB + 255)/256, 256>>>(w_qkv, wqh, wql, QKVC*EMB);
    split_hilo<<<(EMB*EMB + 255)/256, 256>>>(w_proj, wph, wpl, EMB*EMB);

    // 1) QKV projection -> qkv hi/lo
    gemm_big<0><<<dim3(QKVC/128, ROWS/256), 256, SMBIG>>>(
        xh, xl, wqh, wql, nullptr, qh, ql, nullptr);

    // 2) Scores + exp -> p hi/lo + row partial sums (64 per row)
    mma_gemm<1><<<dim3(16, 8, ZTOT), 256, SM1>>>(
        qh, ql, qh, ql, psum, ph, pl, nullptr);

    // 3) 1/rowsum
    inv_rows<<<(AROWS + 255)/256, 256>>>(psum, inv);

    // 4) PV -> oh hi/lo; streams out normalized fp32 attn
    mma_gemm<2><<<dim3(1, 8, ZTOT), 256, SM2>>>(
        ph, pl, qh, ql, attn, ohh, ohl, inv);

    // 5) Output projection + bias -> fp32 out
    gemm_big<3><<<dim3(EMB/128, ROWS/256), 256, SMBIG>>>(
        ohh, ohl, wph, wpl, out, nullptr, nullptr, b_proj);
}

// round 10
// speedup vs baseline: 1.0318x; 1.0318x over previous
#include <cuda_runtime.h>
#include <cuda_bf16.h>
#include <cstdint>

// ---------------------------------------------------------------------------
// Problem constants
// ---------------------------------------------------------------------------
#define BATCHN  8
#define SEQL    1024
#define EMB     768
#define NH      12
#define HD      64
#define ROWS    (BATCHN*SEQL)        // 8192
#define QKVC    (3*EMB)              // 2304
#define ZTOT    (BATCHN*NH)          // 96
#define AROWS   (ZTOT*SEQL)          // 98304
#define K_SCALE 0.125f
#define EXP_OFF 20.0f

// ---------------------------------------------------------------------------
// Device scratch (static globals; allocation-free)
// ---------------------------------------------------------------------------
__device__ __align__(16) __nv_bfloat16 g_x_hi  [ROWS*EMB];
__device__ __align__(16) __nv_bfloat16 g_x_lo  [ROWS*EMB];
__device__ __align__(16) __nv_bfloat16 g_wqkv_hi[QKVC*EMB];
__device__ __align__(16) __nv_bfloat16 g_wqkv_lo[QKVC*EMB];
__device__ __align__(16) __nv_bfloat16 g_wp_hi [EMB*EMB];
__device__ __align__(16) __nv_bfloat16 g_wp_lo [EMB*EMB];
__device__ __align__(16) __nv_bfloat16 g_qkv_hi[(size_t)ROWS*QKVC];
__device__ __align__(16) __nv_bfloat16 g_qkv_lo[(size_t)ROWS*QKVC];
__device__ __align__(16) __nv_bfloat16 g_p_hi  [(size_t)ZTOT*SEQL*SEQL];
__device__ __align__(16) __nv_bfloat16 g_p_lo  [(size_t)ZTOT*SEQL*SEQL];
__device__ __align__(16) __nv_bfloat16 g_oh_hi [ROWS*EMB];
__device__ __align__(16) __nv_bfloat16 g_oh_lo [ROWS*EMB];
__device__ float g_psum[(size_t)AROWS*64];
__device__ float g_inv [AROWS];

// ---------------------------------------------------------------------------
// PTX helpers (all sm_80-era: safe on plain compute_103)
// ---------------------------------------------------------------------------
__device__ __forceinline__ uint32_t smem_u32(const void* p) {
    uint32_t a;
    asm("{ .reg .u64 t; cvta.to.shared.u64 t, %1; cvt.u32.u64 %0, t; }"
        : "=r"(a) : "l"(p));
    return a;
}
__device__ __forceinline__ void cp16(uint32_t dst, const void* src) {
    asm volatile("cp.async.cg.shared.global [%0], [%1], 16;"
                 :: "r"(dst), "l"(src));
}
#define CP_COMMIT() asm volatile("cp.async.commit_group;" ::: "memory")
#define CP_WAIT(n)  asm volatile("cp.async.wait_group %0;" :: "n"(n) : "memory")

__device__ __forceinline__ void ldsm_x4(uint32_t* r, uint32_t addr) {
    asm volatile("ldmatrix.sync.aligned.m8n8.x4.shared.b16 {%0,%1,%2,%3}, [%4];"
        : "=r"(r[0]), "=r"(r[1]), "=r"(r[2]), "=r"(r[3]) : "r"(addr));
}
__device__ __forceinline__ void ldsm_x2(uint32_t* r, uint32_t addr) {
    asm volatile("ldmatrix.sync.aligned.m8n8.x2.shared.b16 {%0,%1}, [%2];"
        : "=r"(r[0]), "=r"(r[1]) : "r"(addr));
}
__device__ __forceinline__ void ldsm_x2t(uint32_t* r, uint32_t addr) {
    asm volatile("ldmatrix.sync.aligned.m8n8.x2.trans.shared.b16 {%0,%1}, [%2];"
        : "=r"(r[0]), "=r"(r[1]) : "r"(addr));
}
__device__ __forceinline__ void mma_bf16(float* c, const uint32_t* a, const uint32_t* b) {
    asm volatile("mma.sync.aligned.m16n8k16.row.col.f32.bf16.bf16.f32 "
        "{%0,%1,%2,%3}, {%4,%5,%6,%7}, {%8,%9}, {%0,%1,%2,%3};"
        : "+f"(c[0]), "+f"(c[1]), "+f"(c[2]), "+f"(c[3])
        : "r"(a[0]), "r"(a[1]), "r"(a[2]), "r"(a[3]), "r"(b[0]), "r"(b[1]));
}

__device__ __forceinline__ uint32_t pack_hi(float a, float b) {
    return ((uint32_t)__bfloat16_as_ushort(__float2bfloat16(b)) << 16) |
            (uint32_t)__bfloat16_as_ushort(__float2bfloat16(a));
}
__device__ __forceinline__ uint32_t pack_lo(float a, float b) {
    __nv_bfloat16 ha = __float2bfloat16(a), hb = __float2bfloat16(b);
    float la = a - __bfloat162float(ha), lb = b - __bfloat162float(hb);
    return ((uint32_t)__bfloat16_as_ushort(__float2bfloat16(lb)) << 16) |
            (uint32_t)__bfloat16_as_ushort(__float2bfloat16(la));
}

// ---------------------------------------------------------------------------
// BIG-TILE projection GEMM (modes 0 and 3): EXACT R8 version (proven).
// 256x128 tile, 8 warps, warp m64 x n64, 3-stage cp.async ring, 1 barrier.
// ---------------------------------------------------------------------------
template<int MODE>
__global__ __launch_bounds__(256)
void gemm_big(const __nv_bfloat16* __restrict__ Ahi_base,
              const __nv_bfloat16* __restrict__ Alo_base,
              const __nv_bfloat16* __restrict__ Bhi_base,
              const __nv_bfloat16* __restrict__ Blo_base,
              float* __restrict__ fout,
              __nv_bfloat16* __restrict__ ohi,
              __nv_bfloat16* __restrict__ olo,
              const float* __restrict__ bias) {
    constexpr int NSTAGE  = EMB / 32;           // 24
    constexpr int STAGES  = 3;
    constexpr int LDS     = 40;
    constexpr int A_BYTES = 256 * LDS * 2;      // 20480
    constexpr int B_BYTES = 128 * LDS * 2;      // 10240
    constexpr int STAGE_B = 2 * A_BYTES + 2 * B_BYTES;   // 61440

    extern __shared__ __align__(16) char dynsmem[];

    const int tid  = threadIdx.x;
    const int lane = tid & 31;
    const int wid  = tid >> 5;
    const int wm   = wid & 3;
    const int wn   = wid >> 2;
    const int l15  = lane & 15;
    const int bx = blockIdx.x, by = blockIdx.y;

    const __nv_bfloat16* Ah = Ahi_base + (long long)by * 256 * EMB;
    const __nv_bfloat16* Al = Alo_base + (long long)by * 256 * EMB;
    const __nv_bfloat16* Bh = Bhi_base + (long long)bx * 128 * EMB;
    const __nv_bfloat16* Bl = Blo_base + (long long)bx * 128 * EMB;

    const int arow = tid >> 2;
    const int acol = (tid & 3) * 8;

    const uint32_t sb = smem_u32(dynsmem);

    auto issue = [&](int s) {
        const uint32_t base = sb + (uint32_t)(s % STAGES) * STAGE_B;
        const long long k0 = (long long)s * 32;
        #pragma unroll
        for (int it = 0; it < 4; it++) {
            const int r = arow + it * 64;
            const uint32_t d = base + (uint32_t)(r * LDS + acol) * 2;
            cp16(d,           Ah + (long long)r * EMB + k0 + acol);
            cp16(d + A_BYTES, Al + (long long)r * EMB + k0 + acol);
        }
        #pragma unroll
        for (int it = 0; it < 2; it++) {
            const int r = arow + it * 64;
            const uint32_t d = base + 2 * A_BYTES + (uint32_t)(r * LDS + acol) * 2;
            cp16(d,           Bh + (long long)r * EMB + k0 + acol);
            cp16(d + B_BYTES, Bl + (long long)r * EMB + k0 + acol);
        }
    };

    float acc[4][8][4];
    #pragma unroll
    for (int i = 0; i < 4; i++)
        #pragma unroll
        for (int j = 0; j < 8; j++)
            #pragma unroll
            for (int e = 0; e < 4; e++) acc[i][j][e] = 0.f;

    issue(0); CP_COMMIT();
    issue(1); CP_COMMIT();

    for (int s = 0; s < NSTAGE; s++) {
        CP_WAIT(1);
        __syncthreads();
        if (s + 2 < NSTAGE) { issue(s + 2); CP_COMMIT(); }

        const uint32_t base = sb + (uint32_t)(s % STAGES) * STAGE_B;
        const uint32_t uAh = base;
        const uint32_t uAl = base + A_BYTES;
        const uint32_t uBh = base + 2 * A_BYTES;
        const uint32_t uBl = base + 2 * A_BYTES + B_BYTES;

        #pragma unroll
        for (int ks = 0; ks < 2; ks++) {
            uint32_t bh[8][2], bl[8][2];
            #pragma unroll
            for (int j = 0; j < 8; j++) {
                const int nr = wn * 64 + j * 8 + (l15 & 7);
                const int kc = ks * 16 + (l15 >> 3) * 8;
                const uint32_t off = (uint32_t)(nr * LDS + kc) * 2;
                ldsm_x2(bh[j], uBh + off);
                ldsm_x2(bl[j], uBl + off);
            }
            #pragma unroll
            for (int i = 0; i < 4; i++) {
                const int ar = wm * 64 + i * 16 + l15;
                const int ac = ks * 16 + (lane >> 4) * 8;
                const uint32_t aoff = (uint32_t)(ar * LDS + ac) * 2;
                uint32_t ah[4], al[4];
                ldsm_x4(ah, uAh + aoff);
                #pragma unroll
                for (int j = 0; j < 8; j++) mma_bf16(acc[i][j], ah, bh[j]);
                ldsm_x4(al, uAl + aoff);
                #pragma unroll
                for (int j = 0; j < 8; j++) mma_bf16(acc[i][j], ah, bl[j]);
                #pragma unroll
                for (int j = 0; j < 8; j++) mma_bf16(acc[i][j], al, bh[j]);
            }
        }
    }

    // ---- epilogue ----
    const int g = lane >> 2, t = lane & 3;
    #pragma unroll
    for (int i = 0; i < 4; i++) {
        const int m0 = by * 256 + wm * 64 + i * 16 + g;
        const int m1 = m0 + 8;
        #pragma unroll
        for (int j = 0; j < 8; j++) {
            const int n = bx * 128 + wn * 64 + j * 8 + 2 * t;
            const float c0 = acc[i][j][0], c1 = acc[i][j][1];
            const float c2 = acc[i][j][2], c3 = acc[i][j][3];
            if (MODE == 0) {
                long long o0 = (long long)m0 * QKVC + n;
                long long o1 = (long long)m1 * QKVC + n;
                *(uint32_t*)(ohi + o0) = pack_hi(c0, c1);
                *(uint32_t*)(olo + o0) = pack_lo(c0, c1);
                *(uint32_t*)(ohi + o1) = pack_hi(c2, c3);
                *(uint32_t*)(olo + o1) = pack_lo(c2, c3);
            } else {
                float2 w0 = { c0 + bias[n], c1 + bias[n + 1] };
                float2 w1 = { c2 + bias[n], c3 + bias[n + 1] };
                *(float2*)(fout + (long long)m0 * EMB + n) = w0;
                *(float2*)(fout + (long long)m1 * EMB + n) = w1;
            }
        }
    }
}

// ---------------------------------------------------------------------------
// Attention kernels (modes 1 and 2), 128x64 tile, 2 CTAs/SM.
// R10: epilogues stage the 128x64 output tile through smem and write gmem
// as coalesced 128B rows (previously scattered 4B stores).
// ---------------------------------------------------------------------------
#define STG_LDS 66   // bf16 row stride for staging (132B, bank-stagger)

template<int MODE>
__global__ __launch_bounds__(256, 2)
void mma_gemm(const __nv_bfloat16* __restrict__ Ahi_base,
              const __nv_bfloat16* __restrict__ Alo_base,
              const __nv_bfloat16* __restrict__ Bhi_base,
              const __nv_bfloat16* __restrict__ Blo_base,
              float* __restrict__ fout,
              __nv_bfloat16* __restrict__ ohi,
              __nv_bfloat16* __restrict__ olo,
              const float* __restrict__ aux) {
    constexpr int NJ      = 2;
    constexpr int KTOT    = (MODE == 1) ? 64 : 1024;
    constexpr int NSTAGE  = KTOT / 32;
    constexpr int STAGES  = (MODE == 1) ? 2 : 3;
    constexpr int LDS_A   = 40;
    constexpr int LDS_B   = (MODE == 2) ? 72 : 40;
    constexpr int A_BYTES = 128 * LDS_A * 2;
    constexpr int B_BYTES = (MODE == 2) ? 32 * LDS_B * 2 : 64 * LDS_B * 2;
    constexpr int STAGE_B = 2 * A_BYTES + 2 * B_BYTES;

    extern __shared__ __align__(16) char dynsmem[];

    const int tid  = threadIdx.x;
    const int lane = tid & 31;
    const int wid  = tid >> 5;
    const int wm   = wid >> 2;
    const int wn   = wid & 3;
    const int l15  = lane & 15;
    const int bx = blockIdx.x, by = blockIdx.y, bz = blockIdx.z;
    const int bb = bz / NH, hh = bz % NH;

    const __nv_bfloat16 *Ah, *Al, *Bh, *Bl;
    long long LDA = 0, LDB = 0;
    if (MODE == 1) {
        LDA = QKVC; LDB = QKVC;
        long long ao = ((long long)bb * SEQL + by * 128) * QKVC + hh * HD;
        long long bo = ((long long)bb * SEQL + bx * 64) * QKVC + EMB + hh * HD;
        Ah = Ahi_base + ao; Al = Alo_base + ao;
        Bh = Bhi_base + bo; Bl = Blo_base + bo;
    } else {
        LDA = SEQL; LDB = QKVC;
        long long ao = (long long)bz * SEQL * SEQL + (long long)by * 128 * SEQL;
        Ah = Ahi_base + ao; Al = Alo_base + ao;
        Bh = Bhi_base;      Bl = Blo_base;
    }
    float* attn_tile = nullptr;
    if (MODE == 2)
        attn_tile = fout + (long long)bz * SEQL * SEQL + (long long)by * 128 * SEQL;
    const long long auxbase = (MODE == 2) ? ((long long)bz * SEQL + by * 128) : 0;

    const int arow0 = tid >> 2;
    const int acol  = (tid & 3) * 8;
    const int arow1 = arow0 + 64;
    const int brow2 = tid >> 3;
    const int bcol2 = (tid & 7) * 8;

    const uint32_t sb = smem_u32(dynsmem);

    auto issue = [&](int s) {
        const uint32_t base = sb + (uint32_t)(s % STAGES) * STAGE_B;
        const long long k0 = (long long)s * 32;
        const uint32_t dA0 = base + (uint32_t)(arow0 * LDS_A + acol) * 2;
        const uint32_t dA1 = base + (uint32_t)(arow1 * LDS_A + acol) * 2;
        cp16(dA0,           Ah + (long long)arow0 * LDA + k0 + acol);
        cp16(dA1,           Ah + (long long)arow1 * LDA + k0 + acol);
        cp16(dA0 + A_BYTES, Al + (long long)arow0 * LDA + k0 + acol);
        cp16(dA1 + A_BYTES, Al + (long long)arow1 * LDA + k0 + acol);
        if (MODE != 2) {
            const uint32_t dB = base + 2 * A_BYTES + (uint32_t)(arow0 * LDS_B + acol) * 2;
            cp16(dB,           Bh + (long long)arow0 * LDB + k0 + acol);
            cp16(dB + B_BYTES, Bl + (long long)arow0 * LDB + k0 + acol);
        } else {
            long long vo = ((long long)bb * SEQL + s * 32 + brow2) * QKVC
                         + 2 * EMB + hh * HD + bcol2;
            const uint32_t dB = base + 2 * A_BYTES + (uint32_t)(brow2 * LDS_B + bcol2) * 2;
            cp16(dB,           Bh + vo);
            cp16(dB + B_BYTES, Bl + vo);
        }
    };

    float acc[4][NJ][4];
    #pragma unroll
    for (int i = 0; i < 4; i++)
        #pragma unroll
        for (int j = 0; j < NJ; j++)
            #pragma unroll
            for (int e = 0; e < 4; e++) acc[i][j][e] = 0.f;

    #pragma unroll
    for (int p = 0; p < STAGES - 1 && p < NSTAGE; p++) { issue(p); CP_COMMIT(); }

    for (int s = 0; s < NSTAGE; s++) {
        CP_WAIT(STAGES - 2);
        __syncthreads();
        if (s + STAGES - 1 < NSTAGE) { issue(s + STAGES - 1); CP_COMMIT(); }

        const int slot = s % STAGES;
        const uint32_t base = sb + (uint32_t)slot * STAGE_B;

        if (MODE == 2) {
            #pragma unroll
            for (int cch = 0; cch < 2; cch++) {
                const int r = (cch == 0) ? arow0 : arow1;
                const char* sp = dynsmem + slot * STAGE_B + (r * LDS_A + acol) * 2;
                uint4 vh = *(const uint4*)sp;
                uint4 vl = *(const uint4*)(sp + A_BYTES);
                const __nv_bfloat16* eh = (const __nv_bfloat16*)&vh;
                const __nv_bfloat16* el = (const __nv_bfloat16*)&vl;
                const float iv = aux[auxbase + r];
                long long ab = (long long)r * SEQL + s * 32 + acol;
                float4 o0, o1;
                o0.x = (__bfloat162float(eh[0]) + __bfloat162float(el[0])) * iv;
                o0.y = (__bfloat162float(eh[1]) + __bfloat162float(el[1])) * iv;
                o0.z = (__bfloat162float(eh[2]) + __bfloat162float(el[2])) * iv;
                o0.w = (__bfloat162float(eh[3]) + __bfloat162float(el[3])) * iv;
                o1.x = (__bfloat162float(eh[4]) + __bfloat162float(el[4])) * iv;
                o1.y = (__bfloat162float(eh[5]) + __bfloat162float(el[5])) * iv;
                o1.z = (__bfloat162float(eh[6]) + __bfloat162float(el[6])) * iv;
                o1.w = (__bfloat162float(eh[7]) + __bfloat162float(el[7])) * iv;
                *(float4*)(attn_tile + ab)     = o0;
                *(float4*)(attn_tile + ab + 4) = o1;
            }
        }

        const uint32_t uAh = base;
        const uint32_t uAl = base + A_BYTES;
        const uint32_t uBh = base + 2 * A_BYTES;
        const uint32_t uBl = base + 2 * A_BYTES + B_BYTES;

        #pragma unroll
        for (int ks = 0; ks < 2; ks++) {
            uint32_t bh[NJ][2], bl[NJ][2];
            #pragma unroll
            for (int j = 0; j < NJ; j++) {
                if (MODE == 2) {
                    const int kr = ks * 16 + l15;
                    const int nc = wn * 16 + j * 8;
                    const uint32_t off = (uint32_t)(kr * LDS_B + nc) * 2;
                    ldsm_x2t(bh[j], uBh + off);
                    ldsm_x2t(bl[j], uBl + off);
                } else {
                    const int nr = wn * 16 + j * 8 + (l15 & 7);
                    const int kc = ks * 16 + (l15 >> 3) * 8;
                    const uint32_t off = (uint32_t)(nr * LDS_B + kc) * 2;
                    ldsm_x2(bh[j], uBh + off);
                    ldsm_x2(bl[j], uBl + off);
                }
            }
            #pragma unroll
            for (int i = 0; i < 4; i++) {
                const int ar = wm * 64 + i * 16 + l15;
                const int ac = ks * 16 + (lane >> 4) * 8;
                const uint32_t aoff = (uint32_t)(ar * LDS_A + ac) * 2;
                uint32_t ah[4], al[4];
                ldsm_x4(ah, uAh + aoff);
                #pragma unroll
                for (int j = 0; j < NJ; j++) mma_bf16(acc[i][j], ah, bh[j]);
                ldsm_x4(al, uAl + aoff);
                #pragma unroll
                for (int j = 0; j < NJ; j++) mma_bf16(acc[i][j], ah, bl[j]);
                #pragma unroll
                for (int j = 0; j < NJ; j++) mma_bf16(acc[i][j], al, bh[j]);
            }
        }
    }

    // ---- epilogue: stage tile in smem, then coalesced 128B-row stores ----
    __syncthreads();   // pipeline smem no longer needed; safe to reuse
    __nv_bfloat16* sOh = (__nv_bfloat16*)dynsmem;        // [128][STG_LDS]
    __nv_bfloat16* sOl = sOh + 128 * STG_LDS;

    const int g = lane >> 2, t = lane & 3;
    #pragma unroll
    for (int i = 0; i < 4; i++) {
        const int r0 = wm * 64 + i * 16 + g;
        const int r1 = r0 + 8;
        const int m0 = by * 128 + r0;
        const int m1 = by * 128 + r1;
        float s0 = 0.f, s1 = 0.f;
        float inv0 = 0.f, inv1 = 0.f;
        if (MODE == 2) { inv0 = aux[auxbase + r0]; inv1 = aux[auxbase + r1]; }

        #pragma unroll
        for (int j = 0; j < NJ; j++) {
            float c0 = acc[i][j][0], c1 = acc[i][j][1];
            float c2 = acc[i][j][2], c3 = acc[i][j][3];
            float v0, v1, v2, v3;
            if (MODE == 1) {
                v0 = __expf(fmaf(c0, K_SCALE, -EXP_OFF));
                v1 = __expf(fmaf(c1, K_SCALE, -EXP_OFF));
                v2 = __expf(fmaf(c2, K_SCALE, -EXP_OFF));
                v3 = __expf(fmaf(c3, K_SCALE, -EXP_OFF));
                s0 += v0 + v1; s1 += v2 + v3;
            } else {
                v0 = c0 * inv0; v1 = c1 * inv0;
                v2 = c2 * inv1; v3 = c3 * inv1;
            }
            const int nloc = wn * 16 + j * 8 + 2 * t;
            *(uint32_t*)(sOh + r0 * STG_LDS + nloc) = pack_hi(v0, v1);
            *(uint32_t*)(sOl + r0 * STG_LDS + nloc) = pack_lo(v0, v1);
            *(uint32_t*)(sOh + r1 * STG_LDS + nloc) = pack_hi(v2, v3);
            *(uint32_t*)(sOl + r1 * STG_LDS + nloc) = pack_lo(v2, v3);
        }
        if (MODE == 1) {
            s0 += __shfl_xor_sync(0xffffffffu, s0, 1);
            s0 += __shfl_xor_sync(0xffffffffu, s0, 2);
            s1 += __shfl_xor_sync(0xffffffffu, s1, 1);
            s1 += __shfl_xor_sync(0xffffffffu, s1, 2);
            if (t == 0) {
                fout[((long long)bz * SEQL + m0) * 64 + bx * 4 + wn] = s0;
                fout[((long long)bz * SEQL + m1) * 64 + bx * 4 + wn] = s1;
            }
        }
    }
    __syncthreads();

    // copy-out: warp per row (32 uint32 = 128B), fully coalesced
    #pragma unroll
    for (int k = 0; k < 16; k++) {
        const int idx  = tid + k * 256;
        const int row  = idx >> 5;
        const int word = idx & 31;
        const uint32_t wh = *(const uint32_t*)(sOh + row * STG_LDS + word * 2);
        const uint32_t wl = *(const uint32_t*)(sOl + row * STG_LDS + word * 2);
        long long go;
        if (MODE == 1)
            go = (((long long)bz * SEQL + by * 128 + row) * SEQL + bx * 64) + word * 2;
        else
            go = (((long long)bb * SEQL + by * 128 + row) * EMB + hh * HD) + word * 2;
        *(uint32_t*)(ohi + go) = wh;
        *(uint32_t*)(olo + go) = wl;
    }
}

// ---------------------------------------------------------------------------
// fp32 -> bf16 hi/lo split
// ---------------------------------------------------------------------------
__global__ void split_hilo(const float* __restrict__ src,
                           __nv_bfloat16* __restrict__ hi,
                           __nv_bfloat16* __restrict__ lo, int n) {
    int i = blockIdx.x * 256 + threadIdx.x;
    if (i < n) {
        float v = src[i];
        __nv_bfloat16 h = __float2bfloat16(v);
        hi[i] = h;
        lo[i] = __float2bfloat16(v - __bfloat162float(h));
    }
}

// 64 partials per row -> 1/sum
__global__ void inv_rows(const float* __restrict__ psum, float* __restrict__ inv) {
    int r = blockIdx.x * 256 + threadIdx.x;
    if (r < AROWS) {
        float s = 0.f;
        #pragma unroll
        for (int j = 0; j < 64; j++) s += psum[(long long)r * 64 + j];
        inv[r] = 1.0f / s;
    }
}

// ---------------------------------------------------------------------------
// Launch
// ---------------------------------------------------------------------------
extern "C" void kernel_launch(void* const* d_in, const int* in_sizes, int n_in,
                              void* d_out, int out_size) {
    (void)in_sizes; (void)n_in; (void)out_size;
    const float* x      = (const float*)d_in[0];
    const float* w_qkv  = (const float*)d_in[1];
    const float* w_proj = (const float*)d_in[2];
    const float* b_proj = (const float*)d_in[3];

    float* out  = (float*)d_out;
    float* attn = out + (long long)ROWS * EMB;

    __nv_bfloat16 *xh, *xl, *wqh, *wql, *wph, *wpl, *qh, *ql, *ph, *pl, *ohh, *ohl;
    float *psum, *inv;
    cudaGetSymbolAddress((void**)&xh,  g_x_hi);    cudaGetSymbolAddress((void**)&xl,  g_x_lo);
    cudaGetSymbolAddress((void**)&wqh, g_wqkv_hi); cudaGetSymbolAddress((void**)&wql, g_wqkv_lo);
    cudaGetSymbolAddress((void**)&wph, g_wp_hi);   cudaGetSymbolAddress((void**)&wpl, g_wp_lo);
    cudaGetSymbolAddress((void**)&qh,  g_qkv_hi);  cudaGetSymbolAddress((void**)&ql,  g_qkv_lo);
    cudaGetSymbolAddress((void**)&ph,  g_p_hi);    cudaGetSymbolAddress((void**)&pl,  g_p_lo);
    cudaGetSymbolAddress((void**)&ohh, g_oh_hi);   cudaGetSymbolAddress((void**)&ohl, g_oh_lo);
    cudaGetSymbolAddress((void**)&psum, g_psum);   cudaGetSymbolAddress((void**)&inv,  g_inv);

    constexpr int SMBIG = 3 * 61440;  // 184320
    constexpr int SM1   = 2 * 30720;  //  61440  (>= staging 33792)
    constexpr int SM2   = 3 * 29696;  //  89088  (>= staging 33792)
    static bool attr_done = false;
    if (!attr_done) {
        cudaFuncSetAttribute(gemm_big<0>, cudaFuncAttributeMaxDynamicSharedMemorySize, SMBIG);
        cudaFuncSetAttribute(gemm_big<3>, cudaFuncAttributeMaxDynamicSharedMemorySize, SMBIG);
        cudaFuncSetAttribute(mma_gemm<1>, cudaFuncAttributeMaxDynamicSharedMemorySize, SM1);
        cudaFuncSetAttribute(mma_gemm<2>, cudaFuncAttributeMaxDynamicSharedMemorySize, SM2);
        attr_done = true;
    }

    // 0) hi/lo splits of fp32 inputs
    split_hilo<<<(ROWS*EMB + 255)/256, 256>>>(x, xh, xl, ROWS*EMB);
    split_hilo<<<(QKVC*EMB + 255)/256, 256>>>(w_qkv, wqh, wql, QKVC*EMB);
    split_hilo<<<(EMB*EMB + 255)/256, 256>>>(w_proj, wph, wpl, EMB*EMB);

    // 1) QKV projection -> qkv hi/lo
    gemm_big<0><<<dim3(QKVC/128, ROWS/256), 256, SMBIG>>>(
        xh, xl, wqh, wql, nullptr, qh, ql, nullptr);

    // 2) Scores + exp -> p hi/lo + row partial sums (64 per row)
    mma_gemm<1><<<dim3(16, 8, ZTOT), 256, SM1>>>(
        qh, ql, qh, ql, psum, ph, pl, nullptr);

    // 3) 1/rowsum
    inv_rows<<<(AROWS + 255)/256, 256>>>(psum, inv);

    // 4) PV -> oh hi/lo; streams out normalized fp32 attn
    mma_gemm<2><<<dim3(1, 8, ZTOT), 256, SM2>>>(
        ph, pl, qh, ql, attn, ohh, ohl, inv);

    // 5) Output projection + bias -> fp32 out
    gemm_big<3><<<dim3(EMB/128, ROWS/256), 256, SMBIG>>>(
        ohh, ohl, wph, wpl, out, nullptr, nullptr, b_proj);
}